// round 4
// baseline (speedup 1.0000x reference)
#include <cuda_runtime.h>
#include <math.h>

#define MAXN 32768

#define FADD __fadd_rn
#define FSUB __fsub_rn
#define FMUL __fmul_rn
#define FDIV __fdiv_rn

// Per-node symmetric covariance scratch, SoA (component-major).
__device__ float g_cov[6 * MAXN];

// ---------------------------------------------------------------------------
// Kernel 1: thread-per-node covariance, sequential edge order, mul-then-add
// (no FMA) — bitwise-matches XLA CPU's outer-product + sequential scatter-add.
// ---------------------------------------------------------------------------
__global__ void cov_kernel(const float* __restrict__ pos,
                           const int* __restrict__ edge_src,
                           int n, int k) {
    int i = blockIdx.x * blockDim.x + threadIdx.x;
    if (i >= n) return;
    float px = pos[3 * i + 0];
    float py = pos[3 * i + 1];
    float pz = pos[3 * i + 2];
    float xx = 0.f, xy = 0.f, xz = 0.f, yy = 0.f, yz = 0.f, zz = 0.f;
    const int4* es4 = (const int4*)(edge_src + (long long)i * k);
    for (int j = 0; j < k / 4; j++) {
        int4 s4 = es4[j];
#pragma unroll
        for (int u = 0; u < 4; u++) {
            int s = (u == 0) ? s4.x : (u == 1) ? s4.y : (u == 2) ? s4.z : s4.w;
            float dx = FSUB(pos[3 * s + 0], px);
            float dy = FSUB(pos[3 * s + 1], py);
            float dz = FSUB(pos[3 * s + 2], pz);
            xx = FADD(xx, FMUL(dx, dx));
            xy = FADD(xy, FMUL(dx, dy));
            xz = FADD(xz, FMUL(dx, dz));
            yy = FADD(yy, FMUL(dy, dy));
            yz = FADD(yz, FMUL(dy, dz));
            zz = FADD(zz, FMUL(dz, dz));
        }
    }
    g_cov[0 * MAXN + i] = xx;
    g_cov[1 * MAXN + i] = xy;
    g_cov[2 * MAXN + i] = xz;
    g_cov[3 * MAXN + i] = yy;
    g_cov[4 * MAXN + i] = yz;
    g_cov[5 * MAXN + i] = zz;
}

// ---------------------------------------------------------------------------
// LAPACK fp32 helpers, netlib-expression-faithful (LAPACK >= 3.10).
// ---------------------------------------------------------------------------
__device__ __forceinline__ float slapy2f(float x, float y) {
    float xa = fabsf(x), ya = fabsf(y);
    float w = fmaxf(xa, ya), z = fminf(xa, ya);
    if (z == 0.f) return w;
    float t = FDIV(z, w);
    return FMUL(w, sqrtf(FADD(1.f, FMUL(t, t))));
}

// LAPACK 3.10+ slartg, fast path: d = sqrt(f*f+g*g); p = 1/d;
// c = |f|*p; s = g*sign(p,f); r = sign(d,f).
__device__ __forceinline__ void slartgf(float f, float g, float& c, float& s,
                                        float& r) {
    if (g == 0.f) {
        c = 1.f; s = 0.f; r = f;
    } else if (f == 0.f) {
        c = 0.f; s = copysignf(1.f, g); r = fabsf(g);
    } else {
        float d = sqrtf(FADD(FMUL(f, f), FMUL(g, g)));
        float p = FDIV(1.f, d);
        c = FMUL(fabsf(f), p);
        s = FMUL(g, copysignf(p, f));
        r = copysignf(d, f);
    }
}

__device__ void slaev2f(float a, float b, float c0, float& rt1, float& rt2,
                        float& cs1, float& sn1) {
    float sm = FADD(a, c0);
    float df = FSUB(a, c0);
    float adf = fabsf(df);
    float tb = FADD(b, b);
    float ab = fabsf(tb);
    float acmx, acmn;
    if (fabsf(a) > fabsf(c0)) { acmx = a; acmn = c0; }
    else { acmx = c0; acmn = a; }
    float rt;
    if (adf > ab) {
        float t = FDIV(ab, adf);
        rt = FMUL(adf, sqrtf(FADD(1.f, FMUL(t, t))));
    } else if (adf < ab) {
        float t = FDIV(adf, ab);
        rt = FMUL(ab, sqrtf(FADD(1.f, FMUL(t, t))));
    } else {
        rt = FMUL(ab, sqrtf(2.f));
    }
    int sgn1;
    if (sm < 0.f) {
        rt1 = FMUL(0.5f, FSUB(sm, rt)); sgn1 = -1;
        rt2 = FSUB(FMUL(FDIV(acmx, rt1), acmn), FMUL(FDIV(b, rt1), b));
    } else if (sm > 0.f) {
        rt1 = FMUL(0.5f, FADD(sm, rt)); sgn1 = 1;
        rt2 = FSUB(FMUL(FDIV(acmx, rt1), acmn), FMUL(FDIV(b, rt1), b));
    } else {
        rt1 = FMUL(0.5f, rt); rt2 = FMUL(-0.5f, rt); sgn1 = 1;
    }
    int sgn2;
    float cs;
    if (df >= 0.f) { cs = FADD(df, rt); sgn2 = 1; }
    else { cs = FSUB(df, rt); sgn2 = -1; }
    float acs = fabsf(cs);
    if (acs > ab) {
        float ct = FDIV(-tb, cs);
        sn1 = FDIV(1.f, sqrtf(FADD(1.f, FMUL(ct, ct))));
        cs1 = FMUL(ct, sn1);
    } else {
        if (ab == 0.f) { cs1 = 1.f; sn1 = 0.f; }
        else {
            float tn = FDIV(-cs, tb);
            cs1 = FDIV(1.f, sqrtf(FADD(1.f, FMUL(tn, tn))));
            sn1 = FMUL(tn, cs1);
        }
    }
    if (sgn1 == sgn2) { float tau = cs1; cs1 = -sn1; sn1 = tau; }
}

// ---------------------------------------------------------------------------
// Kernel 2: thread-per-node LAPACK ssyevd replica for n=3 (jobz='V', uplo='L').
// ssytd2 -> ssteqr('I') -> sormtr, with netlib BLAS expression order.
// ---------------------------------------------------------------------------
__global__ void eig_kernel(const int* __restrict__ num_neighbors,
                           float* __restrict__ out, int n) {
    int gi = blockIdx.x * blockDim.x + threadIdx.x;
    if (gi >= n) return;
    float* o = out + (long long)gi * 9;
    if (num_neighbors[gi] <= 1) {
#pragma unroll
        for (int j = 0; j < 9; j++) o[j] = 0.f;
        return;
    }

    float a00 = g_cov[0 * MAXN + gi];
    float a10 = g_cov[1 * MAXN + gi];
    float a20 = g_cov[2 * MAXN + gi];
    float a11 = g_cov[3 * MAXN + gi];
    float a21 = g_cov[4 * MAXN + gi];
    float a22 = g_cov[5 * MAXN + gi];

    // ================= SSYTD2 (lower), n=3 =================
    float d[4], e[3];
    float tau1 = 0.f, v3 = 0.f;
    {
        float alpha = a10;   // A(2,1)
        float x = a20;       // A(3,1)
        if (x == 0.f) {
            tau1 = 0.f;
            e[1] = alpha;
        } else {
            // slarfg(2, alpha, x)
            float beta = -copysignf(slapy2f(alpha, x), alpha);
            tau1 = FDIV(FSUB(beta, alpha), beta);
            float rcp = FDIV(1.f, FSUB(alpha, beta));  // sscal by 1/(alpha-beta)
            v3 = FMUL(x, rcp);
            e[1] = beta;
            // ssymv (lower, n=2, alpha=tau, x=(1,v3), beta=0):
            float w1 = FADD(FMUL(tau1, a11), FMUL(tau1, FMUL(a21, v3)));
            float w2 = FADD(FMUL(tau1, a21), FMUL(FMUL(tau1, v3), a22));
            // alpha2 = -half*tau*sdot(2, w, v)
            float dot = FADD(w1, FMUL(w2, v3));
            float al2 = -FMUL(FMUL(0.5f, tau1), dot);
            // saxpy: w += al2*v
            w1 = FADD(w1, al2);
            w2 = FADD(w2, FMUL(al2, v3));
            // ssyr2 (lower, alpha=-1): A(i,j) = (A(i,j) + x_i*(-w_j)) + w_i*(-x_j)
            a11 = FADD(FADD(a11, -w1), -w1);
            a21 = FADD(FADD(a21, FMUL(v3, -w1)), -w2);
            a22 = FADD(FADD(a22, FMUL(v3, -w2)), FMUL(w2, -v3));
        }
        e[2] = a21;
        d[1] = a00; d[2] = a11; d[3] = a22;
    }

    // ================= SSTEQR('I'), n=3 =================
    const float eps = 5.9604644775390625e-08f;    // slamch('E') = 2^-24
    const float eps2 = FMUL(eps, eps);
    const float safmin = 1.1754943508222875e-38f; // 2^-126
    const int nn = 3;
    const int nmaxit = nn * 30;
    int jtot = 0;

    float Z[4][4];
#pragma unroll
    for (int i = 1; i <= 3; i++)
#pragma unroll
        for (int j = 1; j <= 3; j++) Z[i][j] = (i == j) ? 1.f : 0.f;

    float wc[3], ws[3];

    int l1 = 1;
    while (l1 <= nn) {
        if (l1 > 1) e[l1 - 1] = 0.f;
        int m = nn;
        for (int mm = l1; mm <= nn - 1; mm++) {
            float tst = fabsf(e[mm]);
            if (tst == 0.f) { m = mm; break; }
            if (tst <= FMUL(FMUL(sqrtf(fabsf(d[mm])), sqrtf(fabsf(d[mm + 1]))),
                            eps)) {
                e[mm] = 0.f; m = mm; break;
            }
        }
        int l = l1, lsv = l, lend = m, lendsv = lend;
        l1 = m + 1;
        if (lend == l) continue;

        float anorm = 0.f;
        for (int i = l; i <= lend; i++) anorm = fmaxf(anorm, fabsf(d[i]));
        for (int i = l; i <= lend - 1; i++) anorm = fmaxf(anorm, fabsf(e[i]));
        if (anorm == 0.f) continue;
        // (ssteqr scale branches unreachable: ssfmin~3e-5 << anorm << ssfmax)

        if (fabsf(d[lend]) < fabsf(d[l])) { lend = lsv; l = lendsv; }

        if (lend > l) {
            // ---------------- QL iteration ----------------
            while (1) {
                int m2 = lend;
                if (l != lend) {
                    for (int mm = l; mm <= lend - 1; mm++) {
                        float tst = FMUL(e[mm], e[mm]);
                        if (tst <= FADD(FMUL(FMUL(eps2, fabsf(d[mm])),
                                             fabsf(d[mm + 1])), safmin)) {
                            m2 = mm; break;
                        }
                    }
                }
                if (m2 < lend) e[m2] = 0.f;
                float p = d[l];
                if (m2 == l) {
                    d[l] = p;
                    l = l + 1;
                    if (l <= lend) continue;
                    break;
                }
                if (m2 == l + 1) {
                    float rt1, rt2, c, s;
                    slaev2f(d[l], e[l], d[l + 1], rt1, rt2, c, s);
#pragma unroll
                    for (int i = 1; i <= nn; i++) {
                        float temp = Z[i][l + 1];
                        Z[i][l + 1] = FSUB(FMUL(c, temp), FMUL(s, Z[i][l]));
                        Z[i][l] = FADD(FMUL(s, temp), FMUL(c, Z[i][l]));
                    }
                    d[l] = rt1; d[l + 1] = rt2; e[l] = 0.f;
                    l = l + 2;
                    if (l <= lend) continue;
                    break;
                }
                if (jtot == nmaxit) break;
                jtot++;
                float g = FDIV(FSUB(d[l + 1], p), FMUL(2.f, e[l]));
                float r = slapy2f(g, 1.f);
                g = FADD(FSUB(d[m2], p),
                         FDIV(e[l], FADD(g, copysignf(r, g))));
                float s = 1.f, c = 1.f;
                p = 0.f;
                for (int i = m2 - 1; i >= l; i--) {
                    float f = FMUL(s, e[i]);
                    float b = FMUL(c, e[i]);
                    slartgf(g, f, c, s, r);
                    if (i != m2 - 1) e[i + 1] = r;
                    g = FSUB(d[i + 1], p);
                    r = FADD(FMUL(FSUB(d[i], g), s), FMUL(FMUL(2.f, c), b));
                    p = FMUL(s, r);
                    d[i + 1] = FADD(g, p);
                    g = FSUB(FMUL(c, r), b);
                    wc[i] = c;
                    ws[i] = -s;
                }
                for (int j = m2 - l; j >= 1; j--) {
                    float cj = wc[l + j - 1], sj = ws[l + j - 1];
                    if (cj != 1.f || sj != 0.f) {
#pragma unroll
                        for (int i = 1; i <= nn; i++) {
                            float temp = Z[i][l + j];
                            Z[i][l + j] =
                                FSUB(FMUL(cj, temp), FMUL(sj, Z[i][l + j - 1]));
                            Z[i][l + j - 1] =
                                FADD(FMUL(sj, temp), FMUL(cj, Z[i][l + j - 1]));
                        }
                    }
                }
                d[l] = FSUB(d[l], p);
                e[l] = g;
            }
        } else {
            // ---------------- QR iteration ----------------
            while (1) {
                int m2 = lend;
                if (l != lend) {
                    for (int mm = l; mm >= lend + 1; mm--) {
                        float tst = FMUL(e[mm - 1], e[mm - 1]);
                        if (tst <= FADD(FMUL(FMUL(eps2, fabsf(d[mm])),
                                             fabsf(d[mm - 1])), safmin)) {
                            m2 = mm; break;
                        }
                    }
                }
                if (m2 > lend) e[m2 - 1] = 0.f;
                float p = d[l];
                if (m2 == l) {
                    d[l] = p;
                    l = l - 1;
                    if (l >= lend) continue;
                    break;
                }
                if (m2 == l - 1) {
                    float rt1, rt2, c, s;
                    slaev2f(d[l - 1], e[l - 1], d[l], rt1, rt2, c, s);
#pragma unroll
                    for (int i = 1; i <= nn; i++) {
                        float temp = Z[i][l];
                        Z[i][l] = FSUB(FMUL(c, temp), FMUL(s, Z[i][l - 1]));
                        Z[i][l - 1] = FADD(FMUL(s, temp), FMUL(c, Z[i][l - 1]));
                    }
                    d[l - 1] = rt1; d[l] = rt2; e[l - 1] = 0.f;
                    l = l - 2;
                    if (l >= lend) continue;
                    break;
                }
                if (jtot == nmaxit) break;
                jtot++;
                float g = FDIV(FSUB(d[l - 1], p), FMUL(2.f, e[l - 1]));
                float r = slapy2f(g, 1.f);
                g = FADD(FSUB(d[m2], p),
                         FDIV(e[l - 1], FADD(g, copysignf(r, g))));
                float s = 1.f, c = 1.f;
                p = 0.f;
                for (int i = m2; i <= l - 1; i++) {
                    float f = FMUL(s, e[i]);
                    float b = FMUL(c, e[i]);
                    slartgf(g, f, c, s, r);
                    if (i != m2) e[i - 1] = r;
                    g = FSUB(d[i], p);
                    r = FADD(FMUL(FSUB(d[i + 1], g), s), FMUL(FMUL(2.f, c), b));
                    p = FMUL(s, r);
                    d[i] = FADD(g, p);
                    g = FSUB(FMUL(c, r), b);
                    wc[i] = c;
                    ws[i] = s;
                }
                for (int j = 1; j <= l - m2; j++) {
                    float cj = wc[m2 + j - 1], sj = ws[m2 + j - 1];
                    if (cj != 1.f || sj != 0.f) {
#pragma unroll
                        for (int i = 1; i <= nn; i++) {
                            float temp = Z[i][m2 + j];
                            Z[i][m2 + j] =
                                FSUB(FMUL(cj, temp), FMUL(sj, Z[i][m2 + j - 1]));
                            Z[i][m2 + j - 1] =
                                FADD(FMUL(sj, temp), FMUL(cj, Z[i][m2 + j - 1]));
                        }
                    }
                }
                d[l] = FSUB(d[l], p);
                e[l - 1] = g;
            }
        }
    }

    // ssteqr final selection sort (ascending, column swaps)
    for (int ii = 2; ii <= nn; ii++) {
        int i = ii - 1;
        int kk = i;
        float p = d[i];
        for (int j = ii; j <= nn; j++) {
            if (d[j] < p) { kk = j; p = d[j]; }
        }
        if (kk != i) {
            d[kk] = d[i];
            d[i] = p;
#pragma unroll
            for (int row = 1; row <= nn; row++) {
                float t = Z[row][i];
                Z[row][i] = Z[row][kk];
                Z[row][kk] = t;
            }
        }
    }

    // ================= SORMTR ('L','L','N'): Z := H(1)*Z =================
    // slarf: w_j = Z(2,j) + v3*Z(3,j); t = -tau*w_j; Z(2,j)+=t; Z(3,j)+=v3*t
    if (tau1 != 0.f) {
#pragma unroll
        for (int j = 1; j <= 3; j++) {
            float w = FADD(Z[2][j], FMUL(Z[3][j], v3));
            float t = FMUL(-tau1, w);
            Z[2][j] = FADD(Z[2][j], t);
            Z[3][j] = FADD(Z[3][j], FMUL(v3, t));
        }
    }

    // frames[a][b] = vecs[b][a]  =>  out[3a+b] = Z[b+1][a+1]
    o[0] = Z[1][1]; o[1] = Z[2][1]; o[2] = Z[3][1];
    o[3] = Z[1][2]; o[4] = Z[2][2]; o[5] = Z[3][2];
    o[6] = Z[1][3]; o[7] = Z[2][3]; o[8] = Z[3][3];
}

// ---------------------------------------------------------------------------
// Launch
// ---------------------------------------------------------------------------
extern "C" void kernel_launch(void* const* d_in, const int* in_sizes, int n_in,
                              void* d_out, int out_size) {
    const float* pos = (const float*)d_in[0];
    const int* edge_src = (const int*)d_in[1];
    // d_in[2] = edge_dst: unused (edge_dst == repeat(arange(n), k))
    const int* num_neighbors = (const int*)d_in[3];

    int n = in_sizes[3];
    int k = in_sizes[1] / n;

    cov_kernel<<<(n + 255) / 256, 256>>>(pos, edge_src, n, k);
    eig_kernel<<<(n + 127) / 128, 128>>>(num_neighbors, (float*)d_out, n);
}

// round 5
// speedup vs baseline: 1.1283x; 1.1283x over previous
#include <cuda_runtime.h>
#include <math.h>

#define MAXN 32768

#define FADD __fadd_rn
#define FSUB __fsub_rn
#define FMUL __fmul_rn
#define FDIV __fdiv_rn

// 16B-aligned padded positions: one LDG.128 per neighbor gather.
__device__ float4 g_pos4[MAXN];

// ---------------------------------------------------------------------------
// Kernel A: pad pos[3*i..3*i+2] -> g_pos4[i] (w unused).
// ---------------------------------------------------------------------------
__global__ void pad_kernel(const float* __restrict__ pos, int n) {
    int i = blockIdx.x * blockDim.x + threadIdx.x;
    if (i >= n) return;
    float4 p;
    p.x = pos[3 * i + 0];
    p.y = pos[3 * i + 1];
    p.z = pos[3 * i + 2];
    p.w = 0.f;
    g_pos4[i] = p;
}

// ---------------------------------------------------------------------------
// LAPACK fp32 helpers, netlib-expression-faithful (LAPACK >= 3.10).
// FROZEN: arithmetic validated at rel_err 3.4e-7 — do not reorder.
// ---------------------------------------------------------------------------
__device__ __forceinline__ float slapy2f(float x, float y) {
    float xa = fabsf(x), ya = fabsf(y);
    float w = fmaxf(xa, ya), z = fminf(xa, ya);
    if (z == 0.f) return w;
    float t = FDIV(z, w);
    return FMUL(w, sqrtf(FADD(1.f, FMUL(t, t))));
}

__device__ __forceinline__ void slartgf(float f, float g, float& c, float& s,
                                        float& r) {
    if (g == 0.f) {
        c = 1.f; s = 0.f; r = f;
    } else if (f == 0.f) {
        c = 0.f; s = copysignf(1.f, g); r = fabsf(g);
    } else {
        float d = sqrtf(FADD(FMUL(f, f), FMUL(g, g)));
        float p = FDIV(1.f, d);
        c = FMUL(fabsf(f), p);
        s = FMUL(g, copysignf(p, f));
        r = copysignf(d, f);
    }
}

__device__ void slaev2f(float a, float b, float c0, float& rt1, float& rt2,
                        float& cs1, float& sn1) {
    float sm = FADD(a, c0);
    float df = FSUB(a, c0);
    float adf = fabsf(df);
    float tb = FADD(b, b);
    float ab = fabsf(tb);
    float acmx, acmn;
    if (fabsf(a) > fabsf(c0)) { acmx = a; acmn = c0; }
    else { acmx = c0; acmn = a; }
    float rt;
    if (adf > ab) {
        float t = FDIV(ab, adf);
        rt = FMUL(adf, sqrtf(FADD(1.f, FMUL(t, t))));
    } else if (adf < ab) {
        float t = FDIV(adf, ab);
        rt = FMUL(ab, sqrtf(FADD(1.f, FMUL(t, t))));
    } else {
        rt = FMUL(ab, sqrtf(2.f));
    }
    int sgn1;
    if (sm < 0.f) {
        rt1 = FMUL(0.5f, FSUB(sm, rt)); sgn1 = -1;
        rt2 = FSUB(FMUL(FDIV(acmx, rt1), acmn), FMUL(FDIV(b, rt1), b));
    } else if (sm > 0.f) {
        rt1 = FMUL(0.5f, FADD(sm, rt)); sgn1 = 1;
        rt2 = FSUB(FMUL(FDIV(acmx, rt1), acmn), FMUL(FDIV(b, rt1), b));
    } else {
        rt1 = FMUL(0.5f, rt); rt2 = FMUL(-0.5f, rt); sgn1 = 1;
    }
    int sgn2;
    float cs;
    if (df >= 0.f) { cs = FADD(df, rt); sgn2 = 1; }
    else { cs = FSUB(df, rt); sgn2 = -1; }
    float acs = fabsf(cs);
    if (acs > ab) {
        float ct = FDIV(-tb, cs);
        sn1 = FDIV(1.f, sqrtf(FADD(1.f, FMUL(ct, ct))));
        cs1 = FMUL(ct, sn1);
    } else {
        if (ab == 0.f) { cs1 = 1.f; sn1 = 0.f; }
        else {
            float tn = FDIV(-cs, tb);
            cs1 = FDIV(1.f, sqrtf(FADD(1.f, FMUL(tn, tn))));
            sn1 = FMUL(tn, cs1);
        }
    }
    if (sgn1 == sgn2) { float tau = cs1; cs1 = -sn1; sn1 = tau; }
}

// ---------------------------------------------------------------------------
// Kernel B (fused): thread-per-node covariance (sequential edge order,
// mul-then-add, registers only) -> LAPACK ssyevd replica (ssytd2 ->
// ssteqr('I') -> sormtr).
// ---------------------------------------------------------------------------
__global__ void fused_kernel(const int* __restrict__ edge_src,
                             const int* __restrict__ num_neighbors,
                             float* __restrict__ out, int n, int k) {
    int gi = blockIdx.x * blockDim.x + threadIdx.x;
    if (gi >= n) return;
    float* o = out + (long long)gi * 9;
    if (num_neighbors[gi] <= 1) {
#pragma unroll
        for (int j = 0; j < 9; j++) o[j] = 0.f;
        return;
    }

    // ================= covariance (frozen arithmetic order) ==============
    float4 pc = g_pos4[gi];
    float px = pc.x, py = pc.y, pz = pc.z;
    float a00 = 0.f, a10 = 0.f, a20 = 0.f, a11 = 0.f, a21 = 0.f, a22 = 0.f;
    const int4* es4 = (const int4*)(edge_src + (long long)gi * k);
#pragma unroll 2
    for (int j = 0; j < k / 4; j++) {
        int4 s4 = es4[j];
        float4 q0 = __ldg(&g_pos4[s4.x]);
        float4 q1 = __ldg(&g_pos4[s4.y]);
        float4 q2 = __ldg(&g_pos4[s4.z]);
        float4 q3 = __ldg(&g_pos4[s4.w]);
#pragma unroll
        for (int u = 0; u < 4; u++) {
            float4 q = (u == 0) ? q0 : (u == 1) ? q1 : (u == 2) ? q2 : q3;
            float dx = FSUB(q.x, px);
            float dy = FSUB(q.y, py);
            float dz = FSUB(q.z, pz);
            a00 = FADD(a00, FMUL(dx, dx));
            a10 = FADD(a10, FMUL(dx, dy));
            a20 = FADD(a20, FMUL(dx, dz));
            a11 = FADD(a11, FMUL(dy, dy));
            a21 = FADD(a21, FMUL(dy, dz));
            a22 = FADD(a22, FMUL(dz, dz));
        }
    }

    // ================= SSYTD2 (lower), n=3 =================
    float d[4], e[3];
    float tau1 = 0.f, v3 = 0.f;
    {
        float alpha = a10;   // A(2,1)
        float x = a20;       // A(3,1)
        if (x == 0.f) {
            tau1 = 0.f;
            e[1] = alpha;
        } else {
            float beta = -copysignf(slapy2f(alpha, x), alpha);
            tau1 = FDIV(FSUB(beta, alpha), beta);
            float rcp = FDIV(1.f, FSUB(alpha, beta));
            v3 = FMUL(x, rcp);
            e[1] = beta;
            float w1 = FADD(FMUL(tau1, a11), FMUL(tau1, FMUL(a21, v3)));
            float w2 = FADD(FMUL(tau1, a21), FMUL(FMUL(tau1, v3), a22));
            float dot = FADD(w1, FMUL(w2, v3));
            float al2 = -FMUL(FMUL(0.5f, tau1), dot);
            w1 = FADD(w1, al2);
            w2 = FADD(w2, FMUL(al2, v3));
            a11 = FADD(FADD(a11, -w1), -w1);
            a21 = FADD(FADD(a21, FMUL(v3, -w1)), -w2);
            a22 = FADD(FADD(a22, FMUL(v3, -w2)), FMUL(w2, -v3));
        }
        e[2] = a21;
        d[1] = a00; d[2] = a11; d[3] = a22;
    }

    // ================= SSTEQR('I'), n=3 =================
    const float eps = 5.9604644775390625e-08f;
    const float eps2 = FMUL(eps, eps);
    const float safmin = 1.1754943508222875e-38f;
    const int nn = 3;
    const int nmaxit = nn * 30;
    int jtot = 0;

    float Z[4][4];
#pragma unroll
    for (int i = 1; i <= 3; i++)
#pragma unroll
        for (int j = 1; j <= 3; j++) Z[i][j] = (i == j) ? 1.f : 0.f;

    float wc[3], ws[3];

    int l1 = 1;
    while (l1 <= nn) {
        if (l1 > 1) e[l1 - 1] = 0.f;
        int m = nn;
        for (int mm = l1; mm <= nn - 1; mm++) {
            float tst = fabsf(e[mm]);
            if (tst == 0.f) { m = mm; break; }
            if (tst <= FMUL(FMUL(sqrtf(fabsf(d[mm])), sqrtf(fabsf(d[mm + 1]))),
                            eps)) {
                e[mm] = 0.f; m = mm; break;
            }
        }
        int l = l1, lsv = l, lend = m, lendsv = lend;
        l1 = m + 1;
        if (lend == l) continue;

        float anorm = 0.f;
        for (int i = l; i <= lend; i++) anorm = fmaxf(anorm, fabsf(d[i]));
        for (int i = l; i <= lend - 1; i++) anorm = fmaxf(anorm, fabsf(e[i]));
        if (anorm == 0.f) continue;

        if (fabsf(d[lend]) < fabsf(d[l])) { lend = lsv; l = lendsv; }

        if (lend > l) {
            // ---------------- QL iteration ----------------
            while (1) {
                int m2 = lend;
                if (l != lend) {
                    for (int mm = l; mm <= lend - 1; mm++) {
                        float tst = FMUL(e[mm], e[mm]);
                        if (tst <= FADD(FMUL(FMUL(eps2, fabsf(d[mm])),
                                             fabsf(d[mm + 1])), safmin)) {
                            m2 = mm; break;
                        }
                    }
                }
                if (m2 < lend) e[m2] = 0.f;
                float p = d[l];
                if (m2 == l) {
                    d[l] = p;
                    l = l + 1;
                    if (l <= lend) continue;
                    break;
                }
                if (m2 == l + 1) {
                    float rt1, rt2, c, s;
                    slaev2f(d[l], e[l], d[l + 1], rt1, rt2, c, s);
#pragma unroll
                    for (int i = 1; i <= nn; i++) {
                        float temp = Z[i][l + 1];
                        Z[i][l + 1] = FSUB(FMUL(c, temp), FMUL(s, Z[i][l]));
                        Z[i][l] = FADD(FMUL(s, temp), FMUL(c, Z[i][l]));
                    }
                    d[l] = rt1; d[l + 1] = rt2; e[l] = 0.f;
                    l = l + 2;
                    if (l <= lend) continue;
                    break;
                }
                if (jtot == nmaxit) break;
                jtot++;
                float g = FDIV(FSUB(d[l + 1], p), FMUL(2.f, e[l]));
                float r = slapy2f(g, 1.f);
                g = FADD(FSUB(d[m2], p),
                         FDIV(e[l], FADD(g, copysignf(r, g))));
                float s = 1.f, c = 1.f;
                p = 0.f;
                for (int i = m2 - 1; i >= l; i--) {
                    float f = FMUL(s, e[i]);
                    float b = FMUL(c, e[i]);
                    slartgf(g, f, c, s, r);
                    if (i != m2 - 1) e[i + 1] = r;
                    g = FSUB(d[i + 1], p);
                    r = FADD(FMUL(FSUB(d[i], g), s), FMUL(FMUL(2.f, c), b));
                    p = FMUL(s, r);
                    d[i + 1] = FADD(g, p);
                    g = FSUB(FMUL(c, r), b);
                    wc[i] = c;
                    ws[i] = -s;
                }
                for (int j = m2 - l; j >= 1; j--) {
                    float cj = wc[l + j - 1], sj = ws[l + j - 1];
                    if (cj != 1.f || sj != 0.f) {
#pragma unroll
                        for (int i = 1; i <= nn; i++) {
                            float temp = Z[i][l + j];
                            Z[i][l + j] =
                                FSUB(FMUL(cj, temp), FMUL(sj, Z[i][l + j - 1]));
                            Z[i][l + j - 1] =
                                FADD(FMUL(sj, temp), FMUL(cj, Z[i][l + j - 1]));
                        }
                    }
                }
                d[l] = FSUB(d[l], p);
                e[l] = g;
            }
        } else {
            // ---------------- QR iteration ----------------
            while (1) {
                int m2 = lend;
                if (l != lend) {
                    for (int mm = l; mm >= lend + 1; mm--) {
                        float tst = FMUL(e[mm - 1], e[mm - 1]);
                        if (tst <= FADD(FMUL(FMUL(eps2, fabsf(d[mm])),
                                             fabsf(d[mm - 1])), safmin)) {
                            m2 = mm; break;
                        }
                    }
                }
                if (m2 > lend) e[m2 - 1] = 0.f;
                float p = d[l];
                if (m2 == l) {
                    d[l] = p;
                    l = l - 1;
                    if (l >= lend) continue;
                    break;
                }
                if (m2 == l - 1) {
                    float rt1, rt2, c, s;
                    slaev2f(d[l - 1], e[l - 1], d[l], rt1, rt2, c, s);
#pragma unroll
                    for (int i = 1; i <= nn; i++) {
                        float temp = Z[i][l];
                        Z[i][l] = FSUB(FMUL(c, temp), FMUL(s, Z[i][l - 1]));
                        Z[i][l - 1] = FADD(FMUL(s, temp), FMUL(c, Z[i][l - 1]));
                    }
                    d[l - 1] = rt1; d[l] = rt2; e[l - 1] = 0.f;
                    l = l - 2;
                    if (l >= lend) continue;
                    break;
                }
                if (jtot == nmaxit) break;
                jtot++;
                float g = FDIV(FSUB(d[l - 1], p), FMUL(2.f, e[l - 1]));
                float r = slapy2f(g, 1.f);
                g = FADD(FSUB(d[m2], p),
                         FDIV(e[l - 1], FADD(g, copysignf(r, g))));
                float s = 1.f, c = 1.f;
                p = 0.f;
                for (int i = m2; i <= l - 1; i++) {
                    float f = FMUL(s, e[i]);
                    float b = FMUL(c, e[i]);
                    slartgf(g, f, c, s, r);
                    if (i != m2) e[i - 1] = r;
                    g = FSUB(d[i], p);
                    r = FADD(FMUL(FSUB(d[i + 1], g), s), FMUL(FMUL(2.f, c), b));
                    p = FMUL(s, r);
                    d[i] = FADD(g, p);
                    g = FSUB(FMUL(c, r), b);
                    wc[i] = c;
                    ws[i] = s;
                }
                for (int j = 1; j <= l - m2; j++) {
                    float cj = wc[m2 + j - 1], sj = ws[m2 + j - 1];
                    if (cj != 1.f || sj != 0.f) {
#pragma unroll
                        for (int i = 1; i <= nn; i++) {
                            float temp = Z[i][m2 + j];
                            Z[i][m2 + j] =
                                FSUB(FMUL(cj, temp), FMUL(sj, Z[i][m2 + j - 1]));
                            Z[i][m2 + j - 1] =
                                FADD(FMUL(sj, temp), FMUL(cj, Z[i][m2 + j - 1]));
                        }
                    }
                }
                d[l] = FSUB(d[l], p);
                e[l - 1] = g;
            }
        }
    }

    // ssteqr final selection sort (ascending, column swaps)
    for (int ii = 2; ii <= nn; ii++) {
        int i = ii - 1;
        int kk = i;
        float p = d[i];
        for (int j = ii; j <= nn; j++) {
            if (d[j] < p) { kk = j; p = d[j]; }
        }
        if (kk != i) {
            d[kk] = d[i];
            d[i] = p;
#pragma unroll
            for (int row = 1; row <= nn; row++) {
                float t = Z[row][i];
                Z[row][i] = Z[row][kk];
                Z[row][kk] = t;
            }
        }
    }

    // ================= SORMTR ('L','L','N'): Z := H(1)*Z =================
    if (tau1 != 0.f) {
#pragma unroll
        for (int j = 1; j <= 3; j++) {
            float w = FADD(Z[2][j], FMUL(Z[3][j], v3));
            float t = FMUL(-tau1, w);
            Z[2][j] = FADD(Z[2][j], t);
            Z[3][j] = FADD(Z[3][j], FMUL(v3, t));
        }
    }

    // frames[a][b] = vecs[b][a]  =>  out[3a+b] = Z[b+1][a+1]
    o[0] = Z[1][1]; o[1] = Z[2][1]; o[2] = Z[3][1];
    o[3] = Z[1][2]; o[4] = Z[2][2]; o[5] = Z[3][2];
    o[6] = Z[1][3]; o[7] = Z[2][3]; o[8] = Z[3][3];
}

// ---------------------------------------------------------------------------
// Launch
// ---------------------------------------------------------------------------
extern "C" void kernel_launch(void* const* d_in, const int* in_sizes, int n_in,
                              void* d_out, int out_size) {
    const float* pos = (const float*)d_in[0];
    const int* edge_src = (const int*)d_in[1];
    // d_in[2] = edge_dst: unused (edge_dst == repeat(arange(n), k))
    const int* num_neighbors = (const int*)d_in[3];

    int n = in_sizes[3];
    int k = in_sizes[1] / n;

    pad_kernel<<<(n + 255) / 256, 256>>>(pos, n);
    fused_kernel<<<(n + 127) / 128, 128>>>(edge_src, num_neighbors,
                                           (float*)d_out, n, k);
}